// round 16
// baseline (speedup 1.0000x reference)
#include <cuda_runtime.h>
#include <cuda_fp16.h>
#include <cstdint>

#define FULL_MASK 0xffffffffu

// pack two f32 -> f16x2 (hi arg in upper 16 bits = .y, lo arg in lower = .x)
__device__ __forceinline__ __half2 pack_h2(float hi, float lo) {
    uint32_t r; asm("cvt.rn.f16x2.f32 %0, %1, %2;" : "=r"(r) : "f"(hi), "f"(lo));
    return *reinterpret_cast<__half2*>(&r);
}
__device__ __forceinline__ __half2 tanh_h2(__half2 v) {
    uint32_t u = *reinterpret_cast<uint32_t*>(&v);
    asm("tanh.approx.f16x2 %0, %1;" : "=r"(u) : "r"(u));
    return *reinterpret_cast<__half2*>(&u);
}
__device__ __forceinline__ uint32_t h2_raw(__half2 v) {
    return *reinterpret_cast<uint32_t*>(&v);
}
__device__ __forceinline__ uint32_t pack_f16(float hi, float lo) {
    uint32_t r; asm("cvt.rn.f16x2.f32 %0, %1, %2;" : "=r"(r) : "f"(hi), "f"(lo));
    return r;
}

// D[16,8] += A[16,16] * B[16,8], f16 in, f32 accum. Row-major A, col-major B.
__device__ __forceinline__ void mma16816(float4& d,
                                         uint32_t a0, uint32_t a1,
                                         uint32_t a2, uint32_t a3,
                                         uint32_t b0, uint32_t b1) {
    asm("mma.sync.aligned.m16n8k16.row.col.f32.f16.f16.f32 "
        "{%0,%1,%2,%3}, {%4,%5,%6,%7}, {%8,%9}, {%0,%1,%2,%3};"
        : "+f"(d.x), "+f"(d.y), "+f"(d.z), "+f"(d.w)
        : "r"(a0), "r"(a1), "r"(a2), "r"(a3), "r"(b0), "r"(b1));
}

// H=32, 4H=128 gates (g-major: n = 32*g + u), I=1, T=512, B=8192.
//
// R16 = R15 with f16x2 activations kept packed end-to-end:
//   per grp: 4 gate tanh + 1 c-tanh as tanh.approx.f16x2 (5 MUFU, was 10);
//   sigmoid = HFMA2(0.5, t, 0.5); i*g = HMUL2; h = HMUL2(so, tanh(c-pair))
//   -> h IS the publish word (no unpack/repack). Only the c update crosses
//   to f32 (2 cvt + 2 fmaf per grp); c stays full precision.
//
// CTA (128 thr, 4 warps) = 16 batches. Warp w owns unit slice jj = w
// (units 8jj..8jj+7) across ALL 4 gates. M16 rows 0-7 = batches base..+7
// (D .x/.y), rows 8-15 = base+8..+15 (.z/.w). Lane l: gr=l>>2, gc=l&3.
// W_hh prescaled single f16; h single f16. 8 MMAs per warp-step.
// C-init = PS*(x*W_ih + b_ih + b_hh) in fp32.
// Per-step CTA-wide exchange: uint2 (grp0, grp1) per lane in a parity ring,
// one __syncthreads, then all 4 slots read back (incl. own).

__global__ void __launch_bounds__(128, 4) lstm_mma_kernel(
    const float* __restrict__ x,      // [B, 512]
    const float* __restrict__ W_ih,   // [128]
    const float* __restrict__ W_hh,   // [128, 32]
    const float* __restrict__ b_ih,   // [128]
    const float* __restrict__ b_hh,   // [128]
    const float* __restrict__ W_lin,  // [32]
    const float* __restrict__ b_lin,  // [1]
    float* __restrict__ out)          // [B]
{
    __shared__ __align__(16) float xs[16][36];      // [batch][step] padded
    __shared__ __align__(8)  uint2 exch[2][4][32];  // [parity][slot jj][lane]
    __shared__ float psum[4][16];                   // epilogue partials

    const int tid = threadIdx.x;
    const int w   = tid >> 5;      // warp = unit slice jj
    const int l   = tid & 31;
    const int jj  = w;
    const int gr  = l >> 2;
    const int gc  = l & 3;

    // ---- per-warp weight fragments in registers (single f16) ----
    uint2 BW[4][2];                // [gate][kfrag]
    float4 qreg[4];                // (PS*W_ih[m], PS*bias[m], ..[m+1]) per gate
    const int u0 = 8 * jj + 2 * gc;
    #pragma unroll
    for (int g = 0; g < 4; ++g) {
        const float ps = (g == 2) ? 1.0f : 0.5f;
        const int n = 8 * (4 * g + jj) + gr;       // B row for this lane
        const float* wr = W_hh + n * 32;
        #pragma unroll
        for (int kk = 0; kk < 2; ++kk) {
            const int k0 = kk * 16 + 2 * gc;
            BW[g][kk] = make_uint2(
                pack_f16(ps * wr[k0 + 1], ps * wr[k0]),
                pack_f16(ps * wr[k0 + 9], ps * wr[k0 + 8]));
        }
        const int m = 32 * g + u0;                 // gate rows for activations
        qreg[g] = make_float4(ps * W_ih[m],     ps * (b_ih[m]     + b_hh[m]),
                              ps * W_ih[m + 1], ps * (b_ih[m + 1] + b_hh[m + 1]));
    }

    const int base = blockIdx.x * 16;
    // x staging: thread loads batch tid/8, steps (tid%8)*4..+3 per 32-chunk
    const float* xb = x + (size_t)(base + (tid >> 3)) * 512 + (tid & 7) * 4;
    float* xw = &xs[tid >> 3][(tid & 7) * 4];

    // A-operand words [kfrag][slot] = uint2(grp0, grp1)
    uint2 Aw[2][2];
    #pragma unroll
    for (int kf = 0; kf < 2; ++kf)
        #pragma unroll
        for (int s = 0; s < 2; ++s) Aw[kf][s] = make_uint2(0u, 0u);

    float cc[2][2] = {};                  // [grp][e], fp32
    __half2 hcur[2] = {__half2(), __half2()};  // last h (packed), per grp
    hcur[0] = pack_h2(0.0f, 0.0f);
    hcur[1] = pack_h2(0.0f, 0.0f);
    const __half2 H05 = __float2half2_rn(0.5f);

    for (int t0 = 0; t0 < 512; t0 += 32) {
        const float4 xv = *reinterpret_cast<const float4*>(xb + t0);
        *reinterpret_cast<float4*>(xw) = xv;
        __syncthreads();

        #pragma unroll 2
        for (int tc = 0; tc < 32; ++tc) {
            const int par = tc & 1;
            const float xtA = xs[gr][tc];
            const float xtB = xs[gr + 8][tc];

            float4 d[4];
            #pragma unroll
            for (int g = 0; g < 4; ++g) {
                d[g].x = fmaf(xtA, qreg[g].x, qreg[g].y);
                d[g].y = fmaf(xtA, qreg[g].z, qreg[g].w);
                d[g].z = fmaf(xtB, qreg[g].x, qreg[g].y);
                d[g].w = fmaf(xtB, qreg[g].z, qreg[g].w);
                #pragma unroll
                for (int kf = 0; kf < 2; ++kf) {
                    mma16816(d[g], Aw[kf][0].x, Aw[kf][0].y,
                                   Aw[kf][1].x, Aw[kf][1].y,
                             BW[g][kf].x, BW[g][kf].y);
                }
            }

            // ---- activations, f16x2 end-to-end (5 MUFU per grp) ----
            #pragma unroll
            for (int grp = 0; grp < 2; ++grp) {
                const float p0i = grp ? d[0].z : d[0].x;
                const float p1i = grp ? d[0].w : d[0].y;
                const float p0f = grp ? d[1].z : d[1].x;
                const float p1f = grp ? d[1].w : d[1].y;
                const float p0g = grp ? d[2].z : d[2].x;
                const float p1g = grp ? d[2].w : d[2].y;
                const float p0o = grp ? d[3].z : d[3].x;
                const float p1o = grp ? d[3].w : d[3].y;

                const __half2 Ti = tanh_h2(pack_h2(p1i, p0i));
                const __half2 Tf = tanh_h2(pack_h2(p1f, p0f));
                const __half2 Tg = tanh_h2(pack_h2(p1g, p0g));
                const __half2 To = tanh_h2(pack_h2(p1o, p0o));

                const __half2 si = __hfma2(H05, Ti, H05);
                const __half2 sf = __hfma2(H05, Tf, H05);
                const __half2 so = __hfma2(H05, To, H05);
                const __half2 ig = __hmul2(si, Tg);

                const float2 igf = __half22float2(ig);
                const float2 sff = __half22float2(sf);
                cc[grp][0] = fmaf(sff.x, cc[grp][0], igf.x);
                cc[grp][1] = fmaf(sff.y, cc[grp][1], igf.y);

                const __half2 tcp = tanh_h2(pack_h2(cc[grp][1], cc[grp][0]));
                hcur[grp] = __hmul2(so, tcp);      // h, already packed f16x2
            }

            // publish this warp's A-word (h already packed)
            exch[par][jj][l] = make_uint2(h2_raw(hcur[0]), h2_raw(hcur[1]));

            __syncthreads();

            #pragma unroll
            for (int kf = 0; kf < 2; ++kf)
                #pragma unroll
                for (int s = 0; s < 2; ++s)
                    Aw[kf][s] = exch[par][2 * kf + s][l];
        }
    }

    // ---- epilogue: out[b] = dot(h, W_lin) + b_lin ----
    const float2 hA = __half22float2(hcur[0]);
    const float2 hB = __half22float2(hcur[1]);
    const float wl0 = W_lin[u0], wl1 = W_lin[u0 + 1];
    float vA = fmaf(hA.x, wl0, hA.y * wl1);
    float vB = fmaf(hB.x, wl0, hB.y * wl1);
    vA += __shfl_xor_sync(FULL_MASK, vA, 1);
    vA += __shfl_xor_sync(FULL_MASK, vA, 2);
    vB += __shfl_xor_sync(FULL_MASK, vB, 1);
    vB += __shfl_xor_sync(FULL_MASK, vB, 2);
    if (gc == 0) {
        psum[jj][gr]     = vA;
        psum[jj][gr + 8] = vB;
    }
    __syncthreads();
    if (w == 0 && l < 16) {
        out[base + l] = psum[0][l] + psum[1][l] + psum[2][l] + psum[3][l]
                        + b_lin[0];
    }
}

extern "C" void kernel_launch(void* const* d_in, const int* in_sizes, int n_in,
                              void* d_out, int out_size) {
    const float* x     = (const float*)d_in[0];
    const float* W_ih  = (const float*)d_in[1];
    const float* W_hh  = (const float*)d_in[2];
    const float* b_ih  = (const float*)d_in[3];
    const float* b_hh  = (const float*)d_in[4];
    const float* W_lin = (const float*)d_in[5];
    const float* b_lin = (const float*)d_in[6];
    float* out = (float*)d_out;

    // 8192 batches / 16 per CTA = 512 CTAs of 128 threads (4 warps).
    lstm_mma_kernel<<<512, 128>>>(x, W_ih, W_hh, b_ih, b_hh, W_lin, b_lin, out);
}